// round 1
// baseline (speedup 1.0000x reference)
#include <cuda_runtime.h>

// ---------------------------------------------------------------------------
// Seq2SeqDaVinciNet: persistent per-batch-tile kernel.
// B=4096, S=64, D=9, H=128, HZ=32.  grid = 128 blocks x 512 threads,
// each block owns MB=32 batch rows and runs the whole recurrence.
// ---------------------------------------------------------------------------

#define kB   4096
#define kS   64
#define kD   9
#define kH   128
#define kHZ  32
#define MB_  32
#define NT_  512
#define kDT  0.1f

// ---- scratch (device globals; no allocation allowed) ----------------------
__device__ float g_EncH[kB * kS * kH];      // [b][s][h]   134MB
__device__ float g_AEt [kB * kH * kS];      // [b][h][s]   134MB (transposed attn_encoder)
__device__ float g_WhhT_enc[kH * 512];      // [k][n]
__device__ float g_WhhT_dec[kH * 512];      // [k][n]
__device__ float g_WihT_dec[137 * 512];     // [k][n]
__device__ float g_VdT[kH * kH];            // [k][ho]

// ---- shared memory layout (float offsets) ---------------------------------
// persistent region
#define OFF_H     0                       // [32][129]
#define OFF_C     (OFF_H   + MB_*129)     // [32][129]
#define OFF_A     (OFF_C   + MB_*129)     // [32][129]  (attn scratch / ctx)
#define OFF_LOG   (OFF_A   + MB_*129)     // [32][65]
#define OFF_ED    (OFF_LOG + MB_*65)      // [32][12]
#define OFF_POS   (OFF_ED  + MB_*12)      // [32][4]
#define OFF_VEL   (OFF_POS + MB_*4)
#define OFF_ACC   (OFF_VEL + MB_*4)
#define OFF_PHYS  (OFF_ACC + MB_*4)       // [32][12]
#define OFF_VE    (OFF_PHYS+ MB_*12)      // 64
#define OFF_VD    (OFF_VE  + 64)          // 128
#define OFF_SC    (OFF_VD  + 128)         // 16: mean(3) std(3) pos_mean(3)
#define OFF_UNION (OFF_SC  + 16)
// encoder-phase union
#define U_ATT   0                          // [32][9][65]
#define U_WE    (U_ATT + 32*9*65)          // [64][257]
#define U_WIH   (U_WE  + 64*257)           // [512][9]
#define U_BIAS  (U_WIH + 512*9)            // [512]
#define ENC_UNION (U_BIAS + 512)
// decoder-phase union (same region)
#define U_WD    0                          // [128][257]
#define U_DBIAS (U_WD + 128*257)           // [512]
#define U_WOUT  (U_DBIAS + 512)            // [3][256]
#define U_BOUT  (U_WOUT + 768)             // 4

#define SMEM_FLOATS (OFF_UNION + ENC_UNION)
#define SMEM_BYTES  (SMEM_FLOATS * 4)      // 224448 B

// ---- math helpers ---------------------------------------------------------
__device__ __forceinline__ float sigm(float x) {
    return __fdividef(1.f, 1.f + __expf(-x));
}
__device__ __forceinline__ float tanhacc(float x) {     // accurate (~1e-7), for LSTM cells
    x = fminf(20.f, fmaxf(-20.f, x));
    float e = __expf(2.f * x);
    return __fdividef(e - 1.f, e + 1.f);
}
__device__ __forceinline__ float tanhfast(float x) {    // MUFU.TANH for attention combs
    float y;
    asm("tanh.approx.f32 %0, %1;" : "=f"(y) : "f"(x));
    return y;
}

// ---- prep: transpose weight matrices for coalesced K-loops ----------------
__global__ void prep_kernel(const float* __restrict__ Whh_e,
                            const float* __restrict__ Whh_d,
                            const float* __restrict__ Wih_d,
                            const float* __restrict__ Vd) {
    int i = blockIdx.x * blockDim.x + threadIdx.x;
    if (i < 128 * 512) {
        int k = i / 512, n = i % 512;
        g_WhhT_enc[i] = Whh_e[n * 128 + k];
        g_WhhT_dec[i] = Whh_d[n * 128 + k];
    }
    if (i < 137 * 512) {
        int k = i / 512, n = i % 512;
        g_WihT_dec[i] = Wih_d[n * 137 + k];
    }
    if (i < 128 * 128) {
        int k = i / 128, ho = i % 128;
        g_VdT[i] = Vd[ho * 128 + k];
    }
}

// ---- main fused kernel ----------------------------------------------------
__global__ __launch_bounds__(NT_, 1)
void davinci_kernel(const float* __restrict__ x,
                    const float* __restrict__ Wih_e,
                    const float* __restrict__ bih_e, const float* __restrict__ bhh_e,
                    const float* __restrict__ We,   const float* __restrict__ Ve,
                    const float* __restrict__ ve,
                    const float* __restrict__ Wd,   const float* __restrict__ vd,
                    const float* __restrict__ bih_d, const float* __restrict__ bhh_d,
                    const float* __restrict__ Wout, const float* __restrict__ bout,
                    const float* __restrict__ smean, const float* __restrict__ sstd,
                    const float* __restrict__ pmean,
                    float* __restrict__ out) {
    extern __shared__ float sm[];
    const int t  = threadIdx.x;
    const int b0 = blockIdx.x * MB_;

    float* sH   = sm + OFF_H;
    float* sC   = sm + OFF_C;
    float* sA   = sm + OFF_A;     // attn scratch; decoder: attn_dec then ctx
    float* sLog = sm + OFF_LOG;
    float* sED  = sm + OFF_ED;
    float* sPos = sm + OFF_POS;
    float* sVel = sm + OFF_VEL;
    float* sAcc = sm + OFF_ACC;
    float* sPhy = sm + OFF_PHYS;
    float* sVe  = sm + OFF_VE;
    float* sVd  = sm + OFF_VD;
    float* sSc  = sm + OFF_SC;
    float* uni  = sm + OFF_UNION;

    // ======================= prologue ======================================
    if (t < 64)  sVe[t] = ve[t];
    if (t < 128) sVd[t] = vd[t];
    if (t < 9)   sSc[t] = (t < 3) ? smean[t] : (t < 6 ? sstd[t - 3] : pmean[t - 6]);

    // stage x rows into union scratch (overlaps future W_e region)
    float* xs = uni + U_WE;                       // [32][64][9] = 18432 floats
    for (int i = t; i < MB_ * kS * kD; i += NT_) {
        int r = i / (kS * kD);
        xs[i] = x[(b0 + r) * kS * kD + (i % (kS * kD))];
    }
    // stage V_e (padded [64][65]) into sA/sLog persistent scratch
    float* sVeM = sA;                             // 4160 floats <= 6208 avail
    for (int i = t; i < 64 * 64; i += NT_) {
        int tt = i / 64, s2 = i % 64;
        sVeM[tt * 65 + s2] = Ve[i];
    }
    // zero h, c
    for (int i = t; i < MB_ * 129; i += NT_) { sH[i] = 0.f; sC[i] = 0.f; }
    __syncthreads();

    // attn_input[r][d][tt] = sum_s V_e[tt][s] * x[r][s][d]
    {
        float* sAtt = uni + U_ATT;
        const int tt = t & 63;
        for (int it = t >> 6; it < MB_ * kD; it += 8) {
            int r = it / 9, d = it % 9;
            float acc = 0.f;
            #pragma unroll 4
            for (int s2 = 0; s2 < 64; s2++)
                acc += sVeM[tt * 65 + s2] * xs[(r * 64 + s2) * 9 + d];
            sAtt[(r * 9 + d) * 65 + tt] = acc;
        }
    }
    // initial physics state from xs (before it is overwritten)
    if (t < MB_) {
        int r = t;
        #pragma unroll
        for (int m = 0; m < 3; m++) {
            float p  = xs[(r * 64 + 63) * 9 + m] + sSc[6 + m];
            float v  = xs[(r * 64 + 63) * 9 + 3 + m] * sSc[3 + m] + sSc[m];
            float pv = xs[(r * 64 + 62) * 9 + 3 + m] * sSc[3 + m] + sSc[m];
            sPos[r * 4 + m] = p;
            sVel[r * 4 + m] = v;
            sAcc[r * 4 + m] = (v - pv) * (1.0f / kDT);
        }
    }
    __syncthreads();

    // load encoder weights (overwrites xs staging)
    float* sWe   = uni + U_WE;     // [64][257]
    float* sWih  = uni + U_WIH;    // [512][9]
    float* sBias = uni + U_BIAS;   // [512]
    for (int i = t; i < 64 * 256; i += NT_) {
        int s2 = i / 256, k = i % 256;
        sWe[s2 * 257 + k] = We[i];
    }
    for (int i = t; i < 512 * 9; i += NT_) sWih[i] = Wih_e[i];
    if (t < 512) sBias[t] = bih_e[t] + bhh_e[t];
    __syncthreads();

    float* sAtt = uni + U_ATT;

    // ======================= encoder loop ==================================
    for (int ts = 0; ts < kS; ts++) {
        // --- stage1: attn_hidden a[r][s] = W_e[s] . [h;c]
        {
            const int s  = t & 63;
            const int r0 = (t >> 6) * 4;
            float a0 = 0.f, a1 = 0.f, a2 = 0.f, a3 = 0.f;
            #pragma unroll 4
            for (int k = 0; k < 128; k++) {
                float w = sWe[s * 257 + k];
                a0 += w * sH[(r0 + 0) * 129 + k];
                a1 += w * sH[(r0 + 1) * 129 + k];
                a2 += w * sH[(r0 + 2) * 129 + k];
                a3 += w * sH[(r0 + 3) * 129 + k];
            }
            #pragma unroll 4
            for (int k = 0; k < 128; k++) {
                float w = sWe[s * 257 + 128 + k];
                a0 += w * sC[(r0 + 0) * 129 + k];
                a1 += w * sC[(r0 + 1) * 129 + k];
                a2 += w * sC[(r0 + 2) * 129 + k];
                a3 += w * sC[(r0 + 3) * 129 + k];
            }
            sA[(r0 + 0) * 129 + s] = a0;
            sA[(r0 + 1) * 129 + s] = a1;
            sA[(r0 + 2) * 129 + s] = a2;
            sA[(r0 + 3) * 129 + s] = a3;
        }
        __syncthreads();
        // --- stage2: e[r][d] = sum_s v_e[s] * tanh(a[r][s] + attn_in[r][d][s])
        if (t < 288) {
            const int d = t >> 5, r = t & 31;
            float acc = 0.f;
            #pragma unroll 4
            for (int s2 = 0; s2 < 64; s2++) {
                float z = sA[r * 129 + s2] + sAtt[(r * 9 + d) * 65 + s2];
                acc += sVe[s2] * tanhfast(z);
            }
            sED[r * 12 + d] = acc;
        }
        __syncthreads();
        // --- stage3: softmax over d; x_tilde = alpha * x_t
        if (t < MB_) {
            const int r = t;
            float mx = -1e30f;
            #pragma unroll
            for (int d = 0; d < 9; d++) mx = fmaxf(mx, sED[r * 12 + d]);
            float ex[9], sum = 0.f;
            #pragma unroll
            for (int d = 0; d < 9; d++) { ex[d] = __expf(sED[r * 12 + d] - mx); sum += ex[d]; }
            float inv = __fdividef(1.f, sum);
            const float* xrow = x + (b0 + r) * (kS * kD) + ts * kD;
            #pragma unroll
            for (int d = 0; d < 9; d++) sED[r * 12 + d] = ex[d] * inv * xrow[d];
        }
        __syncthreads();
        // --- stage4: gates + LSTM update + EncH write; stage5: attn_encoder
        {
            const int j  = t & 127;
            const int r0 = (t >> 7) * 8;
            float a_i[8], a_f[8], a_g[8], a_o[8];
            {
                float bi = sBias[j], bf = sBias[128 + j], bg = sBias[256 + j], bo = sBias[384 + j];
                #pragma unroll
                for (int rr = 0; rr < 8; rr++) { a_i[rr] = bi; a_f[rr] = bf; a_g[rr] = bg; a_o[rr] = bo; }
            }
            #pragma unroll
            for (int d = 0; d < 9; d++) {
                float wi = sWih[j * 9 + d],         wf = sWih[(128 + j) * 9 + d];
                float wg = sWih[(256 + j) * 9 + d], wo = sWih[(384 + j) * 9 + d];
                #pragma unroll
                for (int rr = 0; rr < 8; rr++) {
                    float xv = sED[(r0 + rr) * 12 + d];
                    a_i[rr] += wi * xv; a_f[rr] += wf * xv;
                    a_g[rr] += wg * xv; a_o[rr] += wo * xv;
                }
            }
            #pragma unroll 2
            for (int k = 0; k < 128; k++) {
                const float* wr = g_WhhT_enc + k * 512;
                float wi = wr[j], wf = wr[128 + j], wg = wr[256 + j], wo = wr[384 + j];
                #pragma unroll
                for (int rr = 0; rr < 8; rr++) {
                    float hv = sH[(r0 + rr) * 129 + k];
                    a_i[rr] += wi * hv; a_f[rr] += wf * hv;
                    a_g[rr] += wg * hv; a_o[rr] += wo * hv;
                }
            }
            __syncthreads();
            #pragma unroll
            for (int rr = 0; rr < 8; rr++) {
                int r = r0 + rr;
                float iv = sigm(a_i[rr]), fv = sigm(a_f[rr]);
                float gv = tanhacc(a_g[rr]), ov = sigm(a_o[rr]);
                float cn = fv * sC[r * 129 + j] + iv * gv;
                float hn = ov * tanhacc(cn);
                sC[r * 129 + j] = cn;
                sH[r * 129 + j] = hn;
                g_EncH[((b0 + r) * kS + ts) * kH + j] = hn;
            }
            __syncthreads();
            // stage5: A[r][ho] = V_d[ho] . h  -> store transposed [b][ho][ts]
            float a8[8];
            #pragma unroll
            for (int rr = 0; rr < 8; rr++) a8[rr] = 0.f;
            #pragma unroll 2
            for (int k = 0; k < 128; k++) {
                float w = g_VdT[k * 128 + j];
                #pragma unroll
                for (int rr = 0; rr < 8; rr++) a8[rr] += w * sH[(r0 + rr) * 129 + k];
            }
            #pragma unroll
            for (int rr = 0; rr < 8; rr++)
                g_AEt[((b0 + r0 + rr) * kH + j) * kS + ts] = a8[rr];
        }
        __syncthreads();
    }

    // ======================= decoder weight reload =========================
    float* sWd  = uni + U_WD;      // [128][257]
    float* sDB  = uni + U_DBIAS;
    float* sWo  = uni + U_WOUT;
    float* sBo  = uni + U_BOUT;
    for (int i = t; i < 128 * 256; i += NT_) {
        int ho = i / 256, k = i % 256;
        sWd[ho * 257 + k] = Wd[i];
    }
    if (t < 512) sDB[t] = bih_d[t] + bhh_d[t];
    for (int i = t; i < 768; i += NT_) sWo[i] = Wout[i];
    if (t < 3) sBo[t] = bout[t];
    __syncthreads();

    // ======================= decoder loop ==================================
    for (int st = 0; st < kHZ; st++) {
        // --- s1: attn_dec a[r][ho] = W_d[ho] . [d;c]
        {
            const int ho = t & 127;
            const int r0 = (t >> 7) * 8;
            float acc[8];
            #pragma unroll
            for (int rr = 0; rr < 8; rr++) acc[rr] = 0.f;
            #pragma unroll 2
            for (int k = 0; k < 128; k++) {
                float w = sWd[ho * 257 + k];
                #pragma unroll
                for (int rr = 0; rr < 8; rr++) acc[rr] += w * sH[(r0 + rr) * 129 + k];
            }
            #pragma unroll 2
            for (int k = 0; k < 128; k++) {
                float w = sWd[ho * 257 + 128 + k];
                #pragma unroll
                for (int rr = 0; rr < 8; rr++) acc[rr] += w * sC[(r0 + rr) * 129 + k];
            }
            #pragma unroll
            for (int rr = 0; rr < 8; rr++) sA[(r0 + rr) * 129 + ho] = acc[rr];
        }
        __syncthreads();
        // --- s2: logits[r][s] = sum_ho v_d[ho]*tanh(a[r][ho] + AEt[b][ho][s])
        {
            const int s  = t & 63;
            const int r0 = (t >> 6) * 4;
            float l0 = 0.f, l1 = 0.f, l2 = 0.f, l3 = 0.f;
            #pragma unroll 2
            for (int ho = 0; ho < 128; ho++) {
                float w = sVd[ho];
                float v0 = g_AEt[((b0 + r0 + 0) * kH + ho) * kS + s];
                float v1 = g_AEt[((b0 + r0 + 1) * kH + ho) * kS + s];
                float v2 = g_AEt[((b0 + r0 + 2) * kH + ho) * kS + s];
                float v3 = g_AEt[((b0 + r0 + 3) * kH + ho) * kS + s];
                l0 += w * tanhfast(sA[(r0 + 0) * 129 + ho] + v0);
                l1 += w * tanhfast(sA[(r0 + 1) * 129 + ho] + v1);
                l2 += w * tanhfast(sA[(r0 + 2) * 129 + ho] + v2);
                l3 += w * tanhfast(sA[(r0 + 3) * 129 + ho] + v3);
            }
            sLog[(r0 + 0) * 65 + s] = l0;
            sLog[(r0 + 1) * 65 + s] = l1;
            sLog[(r0 + 2) * 65 + s] = l2;
            sLog[(r0 + 3) * 65 + s] = l3;
        }
        __syncthreads();
        // --- s3: softmax beta over s; build phys vector
        if (t < MB_) {
            const int r = t;
            float mx = -1e30f;
            for (int s2 = 0; s2 < 64; s2++) mx = fmaxf(mx, sLog[r * 65 + s2]);
            float sum = 0.f;
            for (int s2 = 0; s2 < 64; s2++) {
                float e = __expf(sLog[r * 65 + s2] - mx);
                sLog[r * 65 + s2] = e;
                sum += e;
            }
            float inv = __fdividef(1.f, sum);
            for (int s2 = 0; s2 < 64; s2++) sLog[r * 65 + s2] *= inv;
            #pragma unroll
            for (int m = 0; m < 3; m++) {
                sPhy[r * 12 + m]     = sPos[r * 4 + m] - sSc[6 + m];
                sPhy[r * 12 + 3 + m] = __fdividef(sVel[r * 4 + m] - sSc[m], sSc[3 + m]);
                sPhy[r * 12 + 6 + m] = __fdividef(sAcc[r * 4 + m], sSc[3 + m]);
            }
        }
        __syncthreads();
        // --- s4: context[r][ho] = sum_s beta[r][s] * EncH[b][s][ho] (into sA)
        {
            const int ho = t & 127;
            const int r0 = (t >> 7) * 8;
            float acc[8];
            #pragma unroll
            for (int rr = 0; rr < 8; rr++) acc[rr] = 0.f;
            #pragma unroll 2
            for (int s2 = 0; s2 < 64; s2++) {
                #pragma unroll
                for (int rr = 0; rr < 8; rr++) {
                    float hv = g_EncH[((b0 + r0 + rr) * kS + s2) * kH + ho];
                    acc[rr] += sLog[(r0 + rr) * 65 + s2] * hv;
                }
            }
            #pragma unroll
            for (int rr = 0; rr < 8; rr++) sA[(r0 + rr) * 129 + ho] = acc[rr];
        }
        __syncthreads();
        // --- s5: decoder gates + LSTM update
        {
            const int j  = t & 127;
            const int r0 = (t >> 7) * 8;
            float a_i[8], a_f[8], a_g[8], a_o[8];
            {
                float bi = sDB[j], bf = sDB[128 + j], bg = sDB[256 + j], bo = sDB[384 + j];
                #pragma unroll
                for (int rr = 0; rr < 8; rr++) { a_i[rr] = bi; a_f[rr] = bf; a_g[rr] = bg; a_o[rr] = bo; }
            }
            #pragma unroll
            for (int k = 0; k < 9; k++) {
                const float* wr = g_WihT_dec + k * 512;
                float wi = wr[j], wf = wr[128 + j], wg = wr[256 + j], wo = wr[384 + j];
                #pragma unroll
                for (int rr = 0; rr < 8; rr++) {
                    float xv = sPhy[(r0 + rr) * 12 + k];
                    a_i[rr] += wi * xv; a_f[rr] += wf * xv;
                    a_g[rr] += wg * xv; a_o[rr] += wo * xv;
                }
            }
            #pragma unroll 2
            for (int k = 0; k < 128; k++) {
                const float* wr = g_WihT_dec + (9 + k) * 512;
                float wi = wr[j], wf = wr[128 + j], wg = wr[256 + j], wo = wr[384 + j];
                #pragma unroll
                for (int rr = 0; rr < 8; rr++) {
                    float xv = sA[(r0 + rr) * 129 + k];     // context
                    a_i[rr] += wi * xv; a_f[rr] += wf * xv;
                    a_g[rr] += wg * xv; a_o[rr] += wo * xv;
                }
            }
            #pragma unroll 2
            for (int k = 0; k < 128; k++) {
                const float* wr = g_WhhT_dec + k * 512;
                float wi = wr[j], wf = wr[128 + j], wg = wr[256 + j], wo = wr[384 + j];
                #pragma unroll
                for (int rr = 0; rr < 8; rr++) {
                    float hv = sH[(r0 + rr) * 129 + k];
                    a_i[rr] += wi * hv; a_f[rr] += wf * hv;
                    a_g[rr] += wg * hv; a_o[rr] += wo * hv;
                }
            }
            __syncthreads();
            #pragma unroll
            for (int rr = 0; rr < 8; rr++) {
                int r = r0 + rr;
                float iv = sigm(a_i[rr]), fv = sigm(a_f[rr]);
                float gv = tanhacc(a_g[rr]), ov = sigm(a_o[rr]);
                float cn = fv * sC[r * 129 + j] + iv * gv;
                float dn = ov * tanhacc(cn);
                sC[r * 129 + j] = cn;
                sH[r * 129 + j] = dn;
            }
        }
        __syncthreads();
        // --- s6: pred_acc + Verlet + output + state update
        if (t < 96) {
            const int m = t >> 5;       // 0..2
            const int r = t & 31;
            float acc = sBo[m];
            #pragma unroll 4
            for (int k = 0; k < 128; k++) acc += sWo[m * 256 + k] * sH[r * 129 + k];
            #pragma unroll 4
            for (int k = 0; k < 128; k++) acc += sWo[m * 256 + 128 + k] * sA[r * 129 + k];
            float pa   = acc * sSc[3 + m];
            float pos  = sPos[r * 4 + m];
            float vel  = sVel[r * 4 + m];
            float ac   = sAcc[r * 4 + m];
            float posn = pos + vel * kDT + 0.5f * ac * kDT * kDT;
            float veln = vel + 0.5f * (ac + pa) * kDT;
            float* orow = out + ((b0 + r) * kHZ + st) * 9;
            orow[m]     = posn;
            orow[3 + m] = veln;
            orow[6 + m] = pa;
            sPos[r * 4 + m] = posn;
            sVel[r * 4 + m] = veln;
            sAcc[r * 4 + m] = pa;
        }
        __syncthreads();
    }
}

// ---------------------------------------------------------------------------
extern "C" void kernel_launch(void* const* d_in, const int* in_sizes, int n_in,
                              void* d_out, int out_size) {
    const float* x      = (const float*)d_in[0];
    const float* Wih_e  = (const float*)d_in[1];
    const float* Whh_e  = (const float*)d_in[2];
    const float* bih_e  = (const float*)d_in[3];
    const float* bhh_e  = (const float*)d_in[4];
    const float* We     = (const float*)d_in[5];
    const float* Ve     = (const float*)d_in[6];
    const float* ve     = (const float*)d_in[7];
    const float* Wd     = (const float*)d_in[8];
    const float* Vd     = (const float*)d_in[9];
    const float* vd     = (const float*)d_in[10];
    const float* Wih_d  = (const float*)d_in[11];
    const float* Whh_d  = (const float*)d_in[12];
    const float* bih_d  = (const float*)d_in[13];
    const float* bhh_d  = (const float*)d_in[14];
    const float* Wout   = (const float*)d_in[15];
    const float* bout   = (const float*)d_in[16];
    const float* smean  = (const float*)d_in[17];
    const float* sstd   = (const float*)d_in[18];
    const float* pmean  = (const float*)d_in[19];
    float* out = (float*)d_out;

    cudaFuncSetAttribute(davinci_kernel,
                         cudaFuncAttributeMaxDynamicSharedMemorySize, SMEM_BYTES);

    prep_kernel<<<(137 * 512 + 255) / 256, 256>>>(Whh_e, Whh_d, Wih_d, Vd);
    davinci_kernel<<<kB / MB_, NT_, SMEM_BYTES>>>(
        x, Wih_e, bih_e, bhh_e, We, Ve, ve, Wd, vd,
        bih_d, bhh_d, Wout, bout, smean, sstd, pmean, out);
}

// round 4
// speedup vs baseline: 1.3381x; 1.3381x over previous
#include <cuda_runtime.h>

// ---------------------------------------------------------------------------
// Seq2SeqDaVinciNet: persistent per-batch-tile kernel, f32x2-packed edition.
// B=4096, S=64, D=9, H=128, HZ=32.  grid = 128 blocks x 512 threads,
// each block owns MB=32 rows.  Row-PAIRS are packed into 64-bit f32x2 regs.
// ---------------------------------------------------------------------------

#define kB   4096
#define kS   64
#define kD   9
#define kH   128
#define kHZ  32
#define MB_  32
#define NT_  512
#define kDT  0.1f

typedef unsigned long long ull;

// ---- scratch (device globals) ---------------------------------------------
__device__ float  g_EncH[kB * kS * kH];      // [b][s][h]
__device__ float  g_AEt [kB * kH * kS];      // [b][h][s]
__device__ float4 g_Wenc4 [kH * kH];         // [k][j]   gates packed in float4
__device__ float4 g_Wencx4[kD * kH];         // [d][j]
__device__ float4 g_Wdec4 [265 * kH];        // [kk][j]  kk: 9 phys,128 ctx,128 h
__device__ float4 g_Vd4   [32 * kH];         // [k4][ho] 4 k per float4

// ---- shared memory layout (float offsets; all even) -----------------------
#define OFF_HP    0                 // [128][17] float2  (h, pair layout)
#define OFF_CP    4352              // [128][17] float2
#define OFF_AP    8704              // [128][17] float2  (attn / ctx scratch)
#define OFF_LOG   13056             // [64][34]  float   (pair layout)
#define OFF_ED    15232             // [32][12]
#define OFF_EDP   15616             // [9][34]  x_tilde pair layout
#define OFF_PHY   15924             // [9][34]  phys pair layout
#define OFF_POS   16232             // [32][4]
#define OFF_VEL   16360
#define OFF_ACC   16488
#define OFF_VE    16616             // 64
#define OFF_VD    16680             // 128
#define OFF_SC    16808             // 16
#define OFF_BIAS  16824             // 512 (enc bias, later dec bias)
#define OFF_WO    17336             // 768
#define OFF_BO    18104             // 8
#define OFF_UNION 18112
// encoder union: sAtt [32][9][65] @0 (18720), sWeT [256][65] @18720 (16640)
//                xs staging [32*64*9=18432] @18720 (pre-sWeT)
// decoder union: sWdT [256][129] @0 (33024)
#define U_ATT  0
#define U_WET  18720
#define U_XS   18720
#define U_WDT  0
#define UNION_SZ 37152
#define SMEM_FLOATS (OFF_UNION + UNION_SZ)
#define SMEM_BYTES  (SMEM_FLOATS * 4)     // 221056 B

// ---- math helpers ---------------------------------------------------------
__device__ __forceinline__ float sigm(float x) {
    return __fdividef(1.f, 1.f + __expf(-x));
}
__device__ __forceinline__ float tanhacc(float x) {
    x = fminf(20.f, fmaxf(-20.f, x));
    float e = __expf(2.f * x);
    return __fdividef(e - 1.f, e + 1.f);
}
__device__ __forceinline__ float tanhfast(float x) {
    float y; asm("tanh.approx.f32 %0, %1;" : "=f"(y) : "f"(x)); return y;
}
__device__ __forceinline__ ull pk2(float lo, float hi) {
    ull r;
    asm("mov.b64 %0,{%1,%2};" : "=l"(r) : "r"(__float_as_int(lo)), "r"(__float_as_int(hi)));
    return r;
}
__device__ __forceinline__ void upk2(ull v, float& lo, float& hi) {
    int a, b;
    asm("mov.b64 {%0,%1},%2;" : "=r"(a), "=r"(b) : "l"(v));
    lo = __int_as_float(a); hi = __int_as_float(b);
}
__device__ __forceinline__ ull ffma2(ull a, ull b, ull c) {
    ull d; asm("fma.rn.f32x2 %0,%1,%2,%3;" : "=l"(d) : "l"(a), "l"(b), "l"(c)); return d;
}
__device__ __forceinline__ ull ldp(const float* p) {           // LDS.64 pair
    return *reinterpret_cast<const ull*>(p);
}
__device__ __forceinline__ void stp(float* p, ull v) {
    *reinterpret_cast<ull*>(p) = v;
}

// ---- prep: repack weights -------------------------------------------------
__global__ void prep_kernel(const float* __restrict__ Whh_e,
                            const float* __restrict__ Wih_e,
                            const float* __restrict__ Whh_d,
                            const float* __restrict__ Wih_d,
                            const float* __restrict__ Vd) {
    int i = blockIdx.x * blockDim.x + threadIdx.x;
    if (i < 128 * 128) {                    // g_Wenc4[k][j]
        int k = i >> 7, j = i & 127;
        g_Wenc4[i] = make_float4(Whh_e[j * 128 + k], Whh_e[(128 + j) * 128 + k],
                                 Whh_e[(256 + j) * 128 + k], Whh_e[(384 + j) * 128 + k]);
    }
    if (i < 9 * 128) {                      // g_Wencx4[d][j]
        int d = i >> 7, j = i & 127;
        g_Wencx4[i] = make_float4(Wih_e[j * 9 + d], Wih_e[(128 + j) * 9 + d],
                                  Wih_e[(256 + j) * 9 + d], Wih_e[(384 + j) * 9 + d]);
    }
    if (i < 265 * 128) {                    // g_Wdec4[kk][j]
        int kk = i >> 7, j = i & 127;
        if (kk < 137) {
            g_Wdec4[i] = make_float4(Wih_d[j * 137 + kk], Wih_d[(128 + j) * 137 + kk],
                                     Wih_d[(256 + j) * 137 + kk], Wih_d[(384 + j) * 137 + kk]);
        } else {
            int k = kk - 137;
            g_Wdec4[i] = make_float4(Whh_d[j * 128 + k], Whh_d[(128 + j) * 128 + k],
                                     Whh_d[(256 + j) * 128 + k], Whh_d[(384 + j) * 128 + k]);
        }
    }
    if (i < 32 * 128) {                     // g_Vd4[k4][ho]
        int k4 = i >> 7, ho = i & 127;
        g_Vd4[i] = make_float4(Vd[ho * 128 + 4 * k4],     Vd[ho * 128 + 4 * k4 + 1],
                               Vd[ho * 128 + 4 * k4 + 2], Vd[ho * 128 + 4 * k4 + 3]);
    }
}

// ---- main fused kernel ----------------------------------------------------
__global__ __launch_bounds__(NT_, 1)
void davinci_kernel(const float* __restrict__ x,
                    const float* __restrict__ bih_e, const float* __restrict__ bhh_e,
                    const float* __restrict__ We,   const float* __restrict__ Ve,
                    const float* __restrict__ ve,
                    const float* __restrict__ Wd,   const float* __restrict__ vd,
                    const float* __restrict__ bih_d, const float* __restrict__ bhh_d,
                    const float* __restrict__ Wout, const float* __restrict__ bout,
                    const float* __restrict__ smean, const float* __restrict__ sstd,
                    const float* __restrict__ pmean,
                    float* __restrict__ out) {
    extern __shared__ float sm[];
    const int t  = threadIdx.x;
    const int b0 = blockIdx.x * MB_;

    float* sHpf = sm + OFF_HP;     // [128][17] f2 -> float idx (k*17+p)*2
    float* sCpf = sm + OFF_CP;
    float* sApf = sm + OFF_AP;
    float* sLgf = sm + OFF_LOG;    // [64][34]
    float* sED  = sm + OFF_ED;
    float* sEDp = sm + OFF_EDP;    // [9][34]
    float* sPhy = sm + OFF_PHY;    // [9][34]
    float* sPos = sm + OFF_POS;
    float* sVel = sm + OFF_VEL;
    float* sAcc = sm + OFF_ACC;
    float* sVe  = sm + OFF_VE;
    float* sVd  = sm + OFF_VD;
    float* sSc  = sm + OFF_SC;
    float* sBias= sm + OFF_BIAS;
    float* sWo  = sm + OFF_WO;
    float* sBo  = sm + OFF_BO;
    float* uni  = sm + OFF_UNION;

    // ======================= prologue ======================================
    if (t < 64)  sVe[t] = ve[t];
    if (t < 128) sVd[t] = vd[t];
    if (t < 9)   sSc[t] = (t < 3) ? smean[t] : (t < 6 ? sstd[t - 3] : pmean[t - 6]);
    if (t < 512) sBias[t] = bih_e[t] + bhh_e[t];

    float* xs = uni + U_XS;                       // [32][64][9]
    for (int i = t; i < MB_ * kS * kD; i += NT_) {
        int r = i / (kS * kD);
        xs[i] = x[(b0 + r) * kS * kD + (i % (kS * kD))];
    }
    float* sVeM = sApf;                           // [64][65] staging (4160 <= 4352)
    for (int i = t; i < 64 * 64; i += NT_) {
        int tt = i >> 6, s2 = i & 63;
        sVeM[tt * 65 + s2] = Ve[i];
    }
    for (int i = t; i < 4352; i += NT_) { sHpf[i] = 0.f; sCpf[i] = 0.f; }
    __syncthreads();

    // attn_input[r][d][tt] = sum_s V_e[tt][s] * x[r][s][d]
    {
        float* sAtt = uni + U_ATT;
        const int tt = t & 63;
        for (int it = t >> 6; it < MB_ * kD; it += 8) {
            int r = it / 9, d = it % 9;
            float acc = 0.f;
            #pragma unroll 4
            for (int s2 = 0; s2 < 64; s2++)
                acc += sVeM[tt * 65 + s2] * xs[(r * 64 + s2) * 9 + d];
            sAtt[(r * 9 + d) * 65 + tt] = acc;
        }
    }
    if (t < MB_) {
        int r = t;
        #pragma unroll
        for (int m = 0; m < 3; m++) {
            float p  = xs[(r * 64 + 63) * 9 + m] + sSc[6 + m];
            float v  = xs[(r * 64 + 63) * 9 + 3 + m] * sSc[3 + m] + sSc[m];
            float pv = xs[(r * 64 + 62) * 9 + 3 + m] * sSc[3 + m] + sSc[m];
            sPos[r * 4 + m] = p;
            sVel[r * 4 + m] = v;
            sAcc[r * 4 + m] = (v - pv) * (1.0f / kDT);
        }
    }
    __syncthreads();

    // sWeT[k][s] = We[s][k], k in 0..255 (pitch 65)
    float* sWeT = uni + U_WET;
    for (int i = t; i < 64 * 256; i += NT_) {
        int s2 = i >> 8, k = i & 255;
        sWeT[k * 65 + s2] = We[i];
    }
    __syncthreads();

    float* sAtt = uni + U_ATT;

    // ======================= encoder loop ==================================
    for (int ts = 0; ts < kS; ts++) {
        // --- stage1: a[r][s] = W_e[s] . [h;c]  (4 rows = 2 pairs / thread)
        {
            const int s  = t & 63;
            const int pg = (t >> 6) * 2;
            ull a0 = 0ull, a1 = 0ull;
            #pragma unroll 4
            for (int k = 0; k < 128; k++) {
                float w = sWeT[k * 65 + s];
                ull w2 = pk2(w, w);
                a0 = ffma2(w2, ldp(sHpf + (k * 17 + pg) * 2), a0);
                a1 = ffma2(w2, ldp(sHpf + (k * 17 + pg + 1) * 2), a1);
            }
            #pragma unroll 4
            for (int k = 0; k < 128; k++) {
                float w = sWeT[(128 + k) * 65 + s];
                ull w2 = pk2(w, w);
                a0 = ffma2(w2, ldp(sCpf + (k * 17 + pg) * 2), a0);
                a1 = ffma2(w2, ldp(sCpf + (k * 17 + pg + 1) * 2), a1);
            }
            stp(sApf + (s * 17 + pg) * 2, a0);
            stp(sApf + (s * 17 + pg + 1) * 2, a1);
        }
        __syncthreads();
        // --- stage2: e[r][d] = sum_s v_e[s]*tanh(a[r][s] + attn_in[r][d][s])
        if (t < 288) {
            const int d = t >> 5, r = t & 31;
            float acc = 0.f;
            #pragma unroll 4
            for (int s2 = 0; s2 < 64; s2++) {
                float z = sApf[s2 * 34 + r] + sAtt[(r * 9 + d) * 65 + s2];
                acc += sVe[s2] * tanhfast(z);
            }
            sED[r * 12 + d] = acc;
        }
        __syncthreads();
        // --- stage3: softmax over d; x_tilde -> pair layout sEDp[d][r]
        if (t < MB_) {
            const int r = t;
            float mx = -1e30f;
            #pragma unroll
            for (int d = 0; d < 9; d++) mx = fmaxf(mx, sED[r * 12 + d]);
            float ex[9], sum = 0.f;
            #pragma unroll
            for (int d = 0; d < 9; d++) { ex[d] = __expf(sED[r * 12 + d] - mx); sum += ex[d]; }
            float inv = __fdividef(1.f, sum);
            const float* xrow = x + (b0 + r) * (kS * kD) + ts * kD;
            #pragma unroll
            for (int d = 0; d < 9; d++) sEDp[d * 34 + r] = ex[d] * inv * xrow[d];
        }
        __syncthreads();
        // --- stage4: gates + LSTM update; stage5: V_d . h
        {
            const int j  = t & 127;
            const int p0 = (t >> 7) * 4;          // 4 pairs = 8 rows
            ull acc[16];                          // [gate][pair]
            {
                ull bi = pk2(sBias[j], sBias[j]);
                ull bf = pk2(sBias[128 + j], sBias[128 + j]);
                ull bg = pk2(sBias[256 + j], sBias[256 + j]);
                ull bo = pk2(sBias[384 + j], sBias[384 + j]);
                #pragma unroll
                for (int p = 0; p < 4; p++) {
                    acc[p] = bi; acc[4 + p] = bf; acc[8 + p] = bg; acc[12 + p] = bo;
                }
            }
            #pragma unroll
            for (int d = 0; d < 9; d++) {
                float4 w4 = g_Wencx4[d * 128 + j];
                ull wi = pk2(w4.x, w4.x), wf = pk2(w4.y, w4.y);
                ull wg = pk2(w4.z, w4.z), wo = pk2(w4.w, w4.w);
                #pragma unroll
                for (int p = 0; p < 4; p++) {
                    ull xv = ldp(sEDp + d * 34 + 2 * (p0 + p));
                    acc[p]      = ffma2(wi, xv, acc[p]);
                    acc[4 + p]  = ffma2(wf, xv, acc[4 + p]);
                    acc[8 + p]  = ffma2(wg, xv, acc[8 + p]);
                    acc[12 + p] = ffma2(wo, xv, acc[12 + p]);
                }
            }
            #pragma unroll 4
            for (int k = 0; k < 128; k++) {
                float4 w4 = g_Wenc4[k * 128 + j];
                ull wi = pk2(w4.x, w4.x), wf = pk2(w4.y, w4.y);
                ull wg = pk2(w4.z, w4.z), wo = pk2(w4.w, w4.w);
                #pragma unroll
                for (int p = 0; p < 4; p++) {
                    ull hv = ldp(sHpf + (k * 17 + p0 + p) * 2);
                    acc[p]      = ffma2(wi, hv, acc[p]);
                    acc[4 + p]  = ffma2(wf, hv, acc[4 + p]);
                    acc[8 + p]  = ffma2(wg, hv, acc[8 + p]);
                    acc[12 + p] = ffma2(wo, hv, acc[12 + p]);
                }
            }
            __syncthreads();
            #pragma unroll
            for (int p = 0; p < 4; p++) {
                float ai0, ai1, af0, af1, ag0, ag1, ao0, ao1, c0, c1;
                upk2(acc[p], ai0, ai1);  upk2(acc[4 + p], af0, af1);
                upk2(acc[8 + p], ag0, ag1); upk2(acc[12 + p], ao0, ao1);
                upk2(ldp(sCpf + (j * 17 + p0 + p) * 2), c0, c1);
                float cn0 = sigm(af0) * c0 + sigm(ai0) * tanhacc(ag0);
                float cn1 = sigm(af1) * c1 + sigm(ai1) * tanhacc(ag1);
                float hn0 = sigm(ao0) * tanhacc(cn0);
                float hn1 = sigm(ao1) * tanhacc(cn1);
                stp(sCpf + (j * 17 + p0 + p) * 2, pk2(cn0, cn1));
                stp(sHpf + (j * 17 + p0 + p) * 2, pk2(hn0, hn1));
                int r = 2 * (p0 + p);
                g_EncH[((b0 + r) * kS + ts) * kH + j]     = hn0;
                g_EncH[((b0 + r + 1) * kS + ts) * kH + j] = hn1;
            }
            __syncthreads();
            // stage5: A[r][ho] = V_d[ho] . h  -> g_AEt transposed
            ull a5[4] = {0ull, 0ull, 0ull, 0ull};
            #pragma unroll 2
            for (int k4 = 0; k4 < 32; k4++) {
                float4 w4 = g_Vd4[k4 * 128 + j];
                #pragma unroll
                for (int kk = 0; kk < 4; kk++) {
                    float wv = (kk == 0) ? w4.x : (kk == 1) ? w4.y : (kk == 2) ? w4.z : w4.w;
                    ull w2 = pk2(wv, wv);
                    int k = 4 * k4 + kk;
                    #pragma unroll
                    for (int p = 0; p < 4; p++)
                        a5[p] = ffma2(w2, ldp(sHpf + (k * 17 + p0 + p) * 2), a5[p]);
                }
            }
            #pragma unroll
            for (int p = 0; p < 4; p++) {
                float lo, hi; upk2(a5[p], lo, hi);
                int r = 2 * (p0 + p);
                g_AEt[((b0 + r) * kH + j) * kS + ts]     = lo;
                g_AEt[((b0 + r + 1) * kH + j) * kS + ts] = hi;
            }
        }
        __syncthreads();
    }

    // ======================= decoder weight reload =========================
    float* sWdT = uni + U_WDT;                    // [256][129]
    for (int i = t; i < 128 * 256; i += NT_) {
        int ho = i >> 8, k = i & 255;
        sWdT[k * 129 + ho] = Wd[i];
    }
    if (t < 512) sBias[t] = bih_d[t] + bhh_d[t];
    for (int i = t; i < 768; i += NT_) sWo[i] = Wout[i];
    if (t < 3) sBo[t] = bout[t];
    __syncthreads();

    // ======================= decoder loop ==================================
    for (int st = 0; st < kHZ; st++) {
        // --- s1: a[r][ho] = W_d[ho] . [d;c]   (8 rows = 4 pairs)
        {
            const int ho = t & 127;
            const int p0 = (t >> 7) * 4;
            ull a[4] = {0ull, 0ull, 0ull, 0ull};
            #pragma unroll 4
            for (int k = 0; k < 128; k++) {
                float w = sWdT[k * 129 + ho];
                ull w2 = pk2(w, w);
                #pragma unroll
                for (int p = 0; p < 4; p++)
                    a[p] = ffma2(w2, ldp(sHpf + (k * 17 + p0 + p) * 2), a[p]);
            }
            #pragma unroll 4
            for (int k = 0; k < 128; k++) {
                float w = sWdT[(128 + k) * 129 + ho];
                ull w2 = pk2(w, w);
                #pragma unroll
                for (int p = 0; p < 4; p++)
                    a[p] = ffma2(w2, ldp(sCpf + (k * 17 + p0 + p) * 2), a[p]);
            }
            #pragma unroll
            for (int p = 0; p < 4; p++) stp(sApf + (ho * 17 + p0 + p) * 2, a[p]);
        }
        __syncthreads();
        // --- s2: logits[r][s] = sum_ho v_d[ho]*tanh(a[r][ho] + AEt[b][ho][s])
        {
            const int s  = t & 63;
            const int r0 = (t >> 6) * 4;
            float l0 = 0.f, l1 = 0.f, l2 = 0.f, l3 = 0.f;
            const float* aet = g_AEt + (ull)(b0 + r0) * (kH * kS) + s;
            #pragma unroll 2
            for (int ho = 0; ho < 128; ho++) {
                float w = sVd[ho];
                float a0 = sApf[ho * 34 + r0];
                float a1 = sApf[ho * 34 + r0 + 1];
                float a2 = sApf[ho * 34 + r0 + 2];
                float a3 = sApf[ho * 34 + r0 + 3];
                l0 += w * tanhfast(a0 + aet[ho * kS]);
                l1 += w * tanhfast(a1 + aet[(kH + ho) * kS]);
                l2 += w * tanhfast(a2 + aet[(2 * kH + ho) * kS]);
                l3 += w * tanhfast(a3 + aet[(3 * kH + ho) * kS]);
            }
            sLgf[s * 34 + r0]     = l0;
            sLgf[s * 34 + r0 + 1] = l1;
            sLgf[s * 34 + r0 + 2] = l2;
            sLgf[s * 34 + r0 + 3] = l3;
        }
        __syncthreads();
        // --- s3: softmax beta over s; phys vector (pair layouts)
        if (t < MB_) {
            const int r = t;
            float mx = -1e30f;
            for (int s2 = 0; s2 < 64; s2++) mx = fmaxf(mx, sLgf[s2 * 34 + r]);
            float sum = 0.f;
            for (int s2 = 0; s2 < 64; s2++) {
                float e = __expf(sLgf[s2 * 34 + r] - mx);
                sLgf[s2 * 34 + r] = e;
                sum += e;
            }
            float inv = __fdividef(1.f, sum);
            for (int s2 = 0; s2 < 64; s2++) sLgf[s2 * 34 + r] *= inv;
            #pragma unroll
            for (int m = 0; m < 3; m++) {
                sPhy[m * 34 + r]       = sPos[r * 4 + m] - sSc[6 + m];
                sPhy[(3 + m) * 34 + r] = __fdividef(sVel[r * 4 + m] - sSc[m], sSc[3 + m]);
                sPhy[(6 + m) * 34 + r] = __fdividef(sAcc[r * 4 + m], sSc[3 + m]);
            }
        }
        __syncthreads();
        // --- s4: context[r][ho] = sum_s beta[r][s]*EncH  (pairs)
        {
            const int ho = t & 127;
            const int p0 = (t >> 7) * 4;
            ull a[4] = {0ull, 0ull, 0ull, 0ull};
            const float* eh = g_EncH + (ull)(b0 + 2 * p0) * (kS * kH) + ho;
            #pragma unroll 2
            for (int s2 = 0; s2 < 64; s2++) {
                #pragma unroll
                for (int p = 0; p < 4; p++) {
                    ull bv = ldp(sLgf + s2 * 34 + 2 * (p0 + p));
                    float h0 = eh[(2 * p * kS + s2) * kH];
                    float h1 = eh[((2 * p + 1) * kS + s2) * kH];
                    a[p] = ffma2(bv, pk2(h0, h1), a[p]);
                }
            }
            #pragma unroll
            for (int p = 0; p < 4; p++) stp(sApf + (ho * 17 + p0 + p) * 2, a[p]);
        }
        __syncthreads();
        // --- s5: decoder gates + LSTM update
        {
            const int j  = t & 127;
            const int p0 = (t >> 7) * 4;
            ull acc[16];
            {
                ull bi = pk2(sBias[j], sBias[j]);
                ull bf = pk2(sBias[128 + j], sBias[128 + j]);
                ull bg = pk2(sBias[256 + j], sBias[256 + j]);
                ull bo = pk2(sBias[384 + j], sBias[384 + j]);
                #pragma unroll
                for (int p = 0; p < 4; p++) {
                    acc[p] = bi; acc[4 + p] = bf; acc[8 + p] = bg; acc[12 + p] = bo;
                }
            }
            #pragma unroll
            for (int d = 0; d < 9; d++) {
                float4 w4 = g_Wdec4[d * 128 + j];
                ull wi = pk2(w4.x, w4.x), wf = pk2(w4.y, w4.y);
                ull wg = pk2(w4.z, w4.z), wo = pk2(w4.w, w4.w);
                #pragma unroll
                for (int p = 0; p < 4; p++) {
                    ull xv = ldp(sPhy + d * 34 + 2 * (p0 + p));
                    acc[p]      = ffma2(wi, xv, acc[p]);
                    acc[4 + p]  = ffma2(wf, xv, acc[4 + p]);
                    acc[8 + p]  = ffma2(wg, xv, acc[8 + p]);
                    acc[12 + p] = ffma2(wo, xv, acc[12 + p]);
                }
            }
            #pragma unroll 4
            for (int k = 0; k < 128; k++) {         // context part
                float4 w4 = g_Wdec4[(9 + k) * 128 + j];
                ull wi = pk2(w4.x, w4.x), wf = pk2(w4.y, w4.y);
                ull wg = pk2(w4.z, w4.z), wo = pk2(w4.w, w4.w);
                #pragma unroll
                for (int p = 0; p < 4; p++) {
                    ull xv = ldp(sApf + (k * 17 + p0 + p) * 2);
                    acc[p]      = ffma2(wi, xv, acc[p]);
                    acc[4 + p]  = ffma2(wf, xv, acc[4 + p]);
                    acc[8 + p]  = ffma2(wg, xv, acc[8 + p]);
                    acc[12 + p] = ffma2(wo, xv, acc[12 + p]);
                }
            }
            #pragma unroll 4
            for (int k = 0; k < 128; k++) {         // h part
                float4 w4 = g_Wdec4[(137 + k) * 128 + j];
                ull wi = pk2(w4.x, w4.x), wf = pk2(w4.y, w4.y);
                ull wg = pk2(w4.z, w4.z), wo = pk2(w4.w, w4.w);
                #pragma unroll
                for (int p = 0; p < 4; p++) {
                    ull hv = ldp(sHpf + (k * 17 + p0 + p) * 2);
                    acc[p]      = ffma2(wi, hv, acc[p]);
                    acc[4 + p]  = ffma2(wf, hv, acc[4 + p]);
                    acc[8 + p]  = ffma2(wg, hv, acc[8 + p]);
                    acc[12 + p] = ffma2(wo, hv, acc[12 + p]);
                }
            }
            __syncthreads();
            #pragma unroll
            for (int p = 0; p < 4; p++) {
                float ai0, ai1, af0, af1, ag0, ag1, ao0, ao1, c0, c1;
                upk2(acc[p], ai0, ai1);  upk2(acc[4 + p], af0, af1);
                upk2(acc[8 + p], ag0, ag1); upk2(acc[12 + p], ao0, ao1);
                upk2(ldp(sCpf + (j * 17 + p0 + p) * 2), c0, c1);
                float cn0 = sigm(af0) * c0 + sigm(ai0) * tanhacc(ag0);
                float cn1 = sigm(af1) * c1 + sigm(ai1) * tanhacc(ag1);
                float dn0 = sigm(ao0) * tanhacc(cn0);
                float dn1 = sigm(ao1) * tanhacc(cn1);
                stp(sCpf + (j * 17 + p0 + p) * 2, pk2(cn0, cn1));
                stp(sHpf + (j * 17 + p0 + p) * 2, pk2(dn0, dn1));
            }
        }
        __syncthreads();
        // --- s6: pred_acc + Verlet + output
        if (t < 96) {
            const int m = t >> 5;
            const int r = t & 31;
            float acc = sBo[m];
            #pragma unroll 4
            for (int k = 0; k < 128; k++) acc += sWo[m * 256 + k] * sHpf[k * 34 + r];
            #pragma unroll 4
            for (int k = 0; k < 128; k++) acc += sWo[m * 256 + 128 + k] * sApf[k * 34 + r];
            float pa   = acc * sSc[3 + m];
            float pos  = sPos[r * 4 + m];
            float vel  = sVel[r * 4 + m];
            float ac   = sAcc[r * 4 + m];
            float posn = pos + vel * kDT + 0.5f * ac * kDT * kDT;
            float veln = vel + 0.5f * (ac + pa) * kDT;
            float* orow = out + ((b0 + r) * kHZ + st) * 9;
            orow[m]     = posn;
            orow[3 + m] = veln;
            orow[6 + m] = pa;
            sPos[r * 4 + m] = posn;
            sVel[r * 4 + m] = veln;
            sAcc[r * 4 + m] = pa;
        }
        __syncthreads();
    }
}

// ---------------------------------------------------------------------------
extern "C" void kernel_launch(void* const* d_in, const int* in_sizes, int n_in,
                              void* d_out, int out_size) {
    const float* x      = (const float*)d_in[0];
    const float* Wih_e  = (const float*)d_in[1];
    const float* Whh_e  = (const float*)d_in[2];
    const float* bih_e  = (const float*)d_in[3];
    const float* bhh_e  = (const float*)d_in[4];
    const float* We     = (const float*)d_in[5];
    const float* Ve     = (const float*)d_in[6];
    const float* ve     = (const float*)d_in[7];
    const float* Wd     = (const float*)d_in[8];
    const float* Vd     = (const float*)d_in[9];
    const float* vd     = (const float*)d_in[10];
    const float* Wih_d  = (const float*)d_in[11];
    const float* Whh_d  = (const float*)d_in[12];
    const float* bih_d  = (const float*)d_in[13];
    const float* bhh_d  = (const float*)d_in[14];
    const float* Wout   = (const float*)d_in[15];
    const float* bout   = (const float*)d_in[16];
    const float* smean  = (const float*)d_in[17];
    const float* sstd   = (const float*)d_in[18];
    const float* pmean  = (const float*)d_in[19];
    float* out = (float*)d_out;

    cudaFuncSetAttribute(davinci_kernel,
                         cudaFuncAttributeMaxDynamicSharedMemorySize, SMEM_BYTES);

    prep_kernel<<<(265 * 128 + 255) / 256, 256>>>(Whh_e, Wih_e, Whh_d, Wih_d, Vd);
    davinci_kernel<<<kB / MB_, NT_, SMEM_BYTES>>>(
        x, bih_e, bhh_e, We, Ve, ve, Wd, vd,
        bih_d, bhh_d, Wout, bout, smean, sstd, pmean, out);
}

// round 7
// speedup vs baseline: 1.6831x; 1.2578x over previous
#include <cuda_runtime.h>
#include <cuda_bf16.h>

// ---------------------------------------------------------------------------
// Seq2SeqDaVinciNet: persistent per-batch-tile kernel, f32x2-packed edition.
// B=4096, S=64, D=9, H=128, HZ=32.  grid = 128 blocks x 512 threads,
// each block owns MB=32 rows.  Row-PAIRS are packed into 64-bit f32x2 regs.
// Decoder streaming tensors (EncH, AEt) stored as row-pair bf16x2.
// ---------------------------------------------------------------------------

#define kB   4096
#define kS   64
#define kD   9
#define kH   128
#define kHZ  32
#define MB_  32
#define NT_  512
#define kDT  0.1f

typedef unsigned long long ull;

// ---- scratch (device globals) ---------------------------------------------
__device__ __nv_bfloat162 g_EncHbf[(kB/2) * kS * kH];  // [bpair][s][h]   67MB
__device__ __nv_bfloat162 g_AEtbf [(kB/2) * kH * kS];  // [bpair][h][s]   67MB
__device__ float4 g_Wenc4 [kH * kH];         // [k][j]   gates packed in float4
__device__ float4 g_Wencx4[kD * kH];         // [d][j]
__device__ float4 g_Wdec4 [265 * kH];        // [kk][j]  kk: 9 phys,128 ctx,128 h
__device__ float4 g_Vd4   [32 * kH];         // [k4][ho] 4 k per float4

// ---- shared memory layout (float offsets; all even) -----------------------
#define OFF_HP    0                 // [128][17] float2  (h, pair layout)
#define OFF_CP    4352              // [128][17] float2
#define OFF_AP    8704              // [128][17] float2  (attn / ctx scratch)
#define OFF_LOG   13056             // [64][34]  float   (pair layout)
#define OFF_ED    15232             // [32][12]
#define OFF_EDP   15616             // [9][34]  x_tilde pair layout
#define OFF_PHY   15924             // [9][34]  phys pair layout
#define OFF_POS   16232             // [32][4]
#define OFF_VEL   16360
#define OFF_ACC   16488
#define OFF_VE    16616             // 64
#define OFF_VD    16680             // 128
#define OFF_SC    16808             // 16
#define OFF_BIAS  16824             // 512 (enc bias, later dec bias)
#define OFF_WO    17336             // 768
#define OFF_BO    18104             // 8
#define OFF_UNION 18112
#define U_ATT  0
#define U_WET  18720
#define U_XS   18720
#define U_WDT  0
#define UNION_SZ 37152
#define SMEM_FLOATS (OFF_UNION + UNION_SZ)
#define SMEM_BYTES  (SMEM_FLOATS * 4)     // 221056 B

// ---- math helpers ---------------------------------------------------------
__device__ __forceinline__ float sigm(float x) {
    return __fdividef(1.f, 1.f + __expf(-x));
}
__device__ __forceinline__ float tanhacc(float x) {
    x = fminf(20.f, fmaxf(-20.f, x));
    float e = __expf(2.f * x);
    return __fdividef(e - 1.f, e + 1.f);
}
__device__ __forceinline__ float tanhfast(float x) {
    float y; asm("tanh.approx.f32 %0, %1;" : "=f"(y) : "f"(x)); return y;
}
__device__ __forceinline__ ull pk2(float lo, float hi) {
    ull r;
    asm("mov.b64 %0,{%1,%2};" : "=l"(r) : "r"(__float_as_int(lo)), "r"(__float_as_int(hi)));
    return r;
}
__device__ __forceinline__ void upk2(ull v, float& lo, float& hi) {
    int a, b;
    asm("mov.b64 {%0,%1},%2;" : "=r"(a), "=r"(b) : "l"(v));
    lo = __int_as_float(a); hi = __int_as_float(b);
}
__device__ __forceinline__ ull ffma2(ull a, ull b, ull c) {
    ull d; asm("fma.rn.f32x2 %0,%1,%2,%3;" : "=l"(d) : "l"(a), "l"(b), "l"(c)); return d;
}
__device__ __forceinline__ ull ldp(const float* p) {           // LDS.64 pair
    return *reinterpret_cast<const ull*>(p);
}
__device__ __forceinline__ void stp(float* p, ull v) {
    *reinterpret_cast<ull*>(p) = v;
}

// ---- prep: repack weights -------------------------------------------------
__global__ void prep_kernel(const float* __restrict__ Whh_e,
                            const float* __restrict__ Wih_e,
                            const float* __restrict__ Whh_d,
                            const float* __restrict__ Wih_d,
                            const float* __restrict__ Vd) {
    int i = blockIdx.x * blockDim.x + threadIdx.x;
    if (i < 128 * 128) {                    // g_Wenc4[k][j]
        int k = i >> 7, j = i & 127;
        g_Wenc4[i] = make_float4(Whh_e[j * 128 + k], Whh_e[(128 + j) * 128 + k],
                                 Whh_e[(256 + j) * 128 + k], Whh_e[(384 + j) * 128 + k]);
    }
    if (i < 9 * 128) {                      // g_Wencx4[d][j]
        int d = i >> 7, j = i & 127;
        g_Wencx4[i] = make_float4(Wih_e[j * 9 + d], Wih_e[(128 + j) * 9 + d],
                                  Wih_e[(256 + j) * 9 + d], Wih_e[(384 + j) * 9 + d]);
    }
    if (i < 265 * 128) {                    // g_Wdec4[kk][j]
        int kk = i >> 7, j = i & 127;
        if (kk < 137) {
            g_Wdec4[i] = make_float4(Wih_d[j * 137 + kk], Wih_d[(128 + j) * 137 + kk],
                                     Wih_d[(256 + j) * 137 + kk], Wih_d[(384 + j) * 137 + kk]);
        } else {
            int k = kk - 137;
            g_Wdec4[i] = make_float4(Whh_d[j * 128 + k], Whh_d[(128 + j) * 128 + k],
                                     Whh_d[(256 + j) * 128 + k], Whh_d[(384 + j) * 128 + k]);
        }
    }
    if (i < 32 * 128) {                     // g_Vd4[k4][ho]
        int k4 = i >> 7, ho = i & 127;
        g_Vd4[i] = make_float4(Vd[ho * 128 + 4 * k4],     Vd[ho * 128 + 4 * k4 + 1],
                               Vd[ho * 128 + 4 * k4 + 2], Vd[ho * 128 + 4 * k4 + 3]);
    }
}

// ---- main fused kernel ----------------------------------------------------
__global__ __launch_bounds__(NT_, 1)
void davinci_kernel(const float* __restrict__ x,
                    const float* __restrict__ bih_e, const float* __restrict__ bhh_e,
                    const float* __restrict__ We,   const float* __restrict__ Ve,
                    const float* __restrict__ ve,
                    const float* __restrict__ Wd,   const float* __restrict__ vd,
                    const float* __restrict__ bih_d, const float* __restrict__ bhh_d,
                    const float* __restrict__ Wout, const float* __restrict__ bout,
                    const float* __restrict__ smean, const float* __restrict__ sstd,
                    const float* __restrict__ pmean,
                    float* __restrict__ out) {
    extern __shared__ float sm[];
    const int t   = threadIdx.x;
    const int b0  = blockIdx.x * MB_;
    const int bp0 = blockIdx.x * (MB_ / 2);       // pair base

    float* sHpf = sm + OFF_HP;     // [128][17] f2 -> float idx (k*17+p)*2
    float* sCpf = sm + OFF_CP;
    float* sApf = sm + OFF_AP;
    float* sLgf = sm + OFF_LOG;    // [64][34]
    float* sED  = sm + OFF_ED;
    float* sEDp = sm + OFF_EDP;    // [9][34]
    float* sPhy = sm + OFF_PHY;    // [9][34]
    float* sPos = sm + OFF_POS;
    float* sVel = sm + OFF_VEL;
    float* sAcc = sm + OFF_ACC;
    float* sVe  = sm + OFF_VE;
    float* sVd  = sm + OFF_VD;
    float* sSc  = sm + OFF_SC;
    float* sBias= sm + OFF_BIAS;
    float* sWo  = sm + OFF_WO;
    float* sBo  = sm + OFF_BO;
    float* uni  = sm + OFF_UNION;

    // ======================= prologue ======================================
    if (t < 64)  sVe[t] = ve[t];
    if (t < 128) sVd[t] = vd[t];
    if (t < 9)   sSc[t] = (t < 3) ? smean[t] : (t < 6 ? sstd[t - 3] : pmean[t - 6]);
    if (t < 512) sBias[t] = bih_e[t] + bhh_e[t];

    float* xs = uni + U_XS;                       // [32][64][9]
    for (int i = t; i < MB_ * kS * kD; i += NT_) {
        int r = i / (kS * kD);
        xs[i] = x[(b0 + r) * kS * kD + (i % (kS * kD))];
    }
    float* sVeM = sApf;                           // [64][65] staging
    for (int i = t; i < 64 * 64; i += NT_) {
        int tt = i >> 6, s2 = i & 63;
        sVeM[tt * 65 + s2] = Ve[i];
    }
    for (int i = t; i < 4352; i += NT_) { sHpf[i] = 0.f; sCpf[i] = 0.f; }
    __syncthreads();

    // attn_input[r][d][tt] = sum_s V_e[tt][s] * x[r][s][d]
    {
        float* sAtt = uni + U_ATT;
        const int tt = t & 63;
        for (int it = t >> 6; it < MB_ * kD; it += 8) {
            int r = it / 9, d = it % 9;
            float acc = 0.f;
            #pragma unroll 4
            for (int s2 = 0; s2 < 64; s2++)
                acc += sVeM[tt * 65 + s2] * xs[(r * 64 + s2) * 9 + d];
            sAtt[(r * 9 + d) * 65 + tt] = acc;
        }
    }
    if (t < MB_) {
        int r = t;
        #pragma unroll
        for (int m = 0; m < 3; m++) {
            float p  = xs[(r * 64 + 63) * 9 + m] + sSc[6 + m];
            float v  = xs[(r * 64 + 63) * 9 + 3 + m] * sSc[3 + m] + sSc[m];
            float pv = xs[(r * 64 + 62) * 9 + 3 + m] * sSc[3 + m] + sSc[m];
            sPos[r * 4 + m] = p;
            sVel[r * 4 + m] = v;
            sAcc[r * 4 + m] = (v - pv) * (1.0f / kDT);
        }
    }
    __syncthreads();

    // sWeT[k][s] = We[s][k], k in 0..255 (pitch 65)
    float* sWeT = uni + U_WET;
    for (int i = t; i < 64 * 256; i += NT_) {
        int s2 = i >> 8, k = i & 255;
        sWeT[k * 65 + s2] = We[i];
    }
    __syncthreads();

    float* sAtt = uni + U_ATT;

    // ======================= encoder loop ==================================
    for (int ts = 0; ts < kS; ts++) {
        // --- stage1: a[r][s] = W_e[s] . [h;c]  (4 rows = 2 pairs / thread)
        {
            const int s  = t & 63;
            const int pg = (t >> 6) * 2;
            ull a0 = 0ull, a1 = 0ull;
            #pragma unroll 4
            for (int k = 0; k < 128; k++) {
                float w = sWeT[k * 65 + s];
                ull w2 = pk2(w, w);
                a0 = ffma2(w2, ldp(sHpf + (k * 17 + pg) * 2), a0);
                a1 = ffma2(w2, ldp(sHpf + (k * 17 + pg + 1) * 2), a1);
            }
            #pragma unroll 4
            for (int k = 0; k < 128; k++) {
                float w = sWeT[(128 + k) * 65 + s];
                ull w2 = pk2(w, w);
                a0 = ffma2(w2, ldp(sCpf + (k * 17 + pg) * 2), a0);
                a1 = ffma2(w2, ldp(sCpf + (k * 17 + pg + 1) * 2), a1);
            }
            stp(sApf + (s * 17 + pg) * 2, a0);
            stp(sApf + (s * 17 + pg + 1) * 2, a1);
        }
        __syncthreads();
        // --- stage2: e[r][d] = sum_s v_e[s]*tanh(a[r][s] + attn_in[r][d][s])
        if (t < 288) {
            const int d = t >> 5, r = t & 31;
            float acc = 0.f;
            #pragma unroll 4
            for (int s2 = 0; s2 < 64; s2++) {
                float z = sApf[s2 * 34 + r] + sAtt[(r * 9 + d) * 65 + s2];
                acc += sVe[s2] * tanhfast(z);
            }
            sED[r * 12 + d] = acc;
        }
        __syncthreads();
        // --- stage3: softmax over d; x_tilde -> pair layout sEDp[d][r]
        if (t < MB_) {
            const int r = t;
            float mx = -1e30f;
            #pragma unroll
            for (int d = 0; d < 9; d++) mx = fmaxf(mx, sED[r * 12 + d]);
            float ex[9], sum = 0.f;
            #pragma unroll
            for (int d = 0; d < 9; d++) { ex[d] = __expf(sED[r * 12 + d] - mx); sum += ex[d]; }
            float inv = __fdividef(1.f, sum);
            const float* xrow = x + (b0 + r) * (kS * kD) + ts * kD;
            #pragma unroll
            for (int d = 0; d < 9; d++) sEDp[d * 34 + r] = ex[d] * inv * xrow[d];
        }
        __syncthreads();
        // --- stage4: gates + LSTM update; stage5: V_d . h
        {
            const int j  = t & 127;
            const int p0 = (t >> 7) * 4;          // 4 pairs = 8 rows
            ull acc[16];                          // [gate][pair]
            {
                ull bi = pk2(sBias[j], sBias[j]);
                ull bf = pk2(sBias[128 + j], sBias[128 + j]);
                ull bg = pk2(sBias[256 + j], sBias[256 + j]);
                ull bo = pk2(sBias[384 + j], sBias[384 + j]);
                #pragma unroll
                for (int p = 0; p < 4; p++) {
                    acc[p] = bi; acc[4 + p] = bf; acc[8 + p] = bg; acc[12 + p] = bo;
                }
            }
            #pragma unroll
            for (int d = 0; d < 9; d++) {
                float4 w4 = g_Wencx4[d * 128 + j];
                ull wi = pk2(w4.x, w4.x), wf = pk2(w4.y, w4.y);
                ull wg = pk2(w4.z, w4.z), wo = pk2(w4.w, w4.w);
                #pragma unroll
                for (int p = 0; p < 4; p++) {
                    ull xv = ldp(sEDp + d * 34 + 2 * (p0 + p));
                    acc[p]      = ffma2(wi, xv, acc[p]);
                    acc[4 + p]  = ffma2(wf, xv, acc[4 + p]);
                    acc[8 + p]  = ffma2(wg, xv, acc[8 + p]);
                    acc[12 + p] = ffma2(wo, xv, acc[12 + p]);
                }
            }
            #pragma unroll 4
            for (int k = 0; k < 128; k++) {
                float4 w4 = g_Wenc4[k * 128 + j];
                ull wi = pk2(w4.x, w4.x), wf = pk2(w4.y, w4.y);
                ull wg = pk2(w4.z, w4.z), wo = pk2(w4.w, w4.w);
                #pragma unroll
                for (int p = 0; p < 4; p++) {
                    ull hv = ldp(sHpf + (k * 17 + p0 + p) * 2);
                    acc[p]      = ffma2(wi, hv, acc[p]);
                    acc[4 + p]  = ffma2(wf, hv, acc[4 + p]);
                    acc[8 + p]  = ffma2(wg, hv, acc[8 + p]);
                    acc[12 + p] = ffma2(wo, hv, acc[12 + p]);
                }
            }
            __syncthreads();
            #pragma unroll
            for (int p = 0; p < 4; p++) {
                float ai0, ai1, af0, af1, ag0, ag1, ao0, ao1, c0, c1;
                upk2(acc[p], ai0, ai1);  upk2(acc[4 + p], af0, af1);
                upk2(acc[8 + p], ag0, ag1); upk2(acc[12 + p], ao0, ao1);
                upk2(ldp(sCpf + (j * 17 + p0 + p) * 2), c0, c1);
                float cn0 = sigm(af0) * c0 + sigm(ai0) * tanhacc(ag0);
                float cn1 = sigm(af1) * c1 + sigm(ai1) * tanhacc(ag1);
                float hn0 = sigm(ao0) * tanhacc(cn0);
                float hn1 = sigm(ao1) * tanhacc(cn1);
                stp(sCpf + (j * 17 + p0 + p) * 2, pk2(cn0, cn1));
                stp(sHpf + (j * 17 + p0 + p) * 2, pk2(hn0, hn1));
                g_EncHbf[((size_t)(bp0 + p0 + p) * kS + ts) * kH + j] =
                    __float22bfloat162_rn(make_float2(hn0, hn1));
            }
            __syncthreads();
            // stage5: A[r][ho] = V_d[ho] . h  -> g_AEtbf transposed, pair bf16
            ull a5[4] = {0ull, 0ull, 0ull, 0ull};
            #pragma unroll 2
            for (int k4 = 0; k4 < 32; k4++) {
                float4 w4 = g_Vd4[k4 * 128 + j];
                #pragma unroll
                for (int kk = 0; kk < 4; kk++) {
                    float wv = (kk == 0) ? w4.x : (kk == 1) ? w4.y : (kk == 2) ? w4.z : w4.w;
                    ull w2 = pk2(wv, wv);
                    int k = 4 * k4 + kk;
                    #pragma unroll
                    for (int p = 0; p < 4; p++)
                        a5[p] = ffma2(w2, ldp(sHpf + (k * 17 + p0 + p) * 2), a5[p]);
                }
            }
            #pragma unroll
            for (int p = 0; p < 4; p++) {
                float lo, hi; upk2(a5[p], lo, hi);
                g_AEtbf[((size_t)(bp0 + p0 + p) * kH + j) * kS + ts] =
                    __float22bfloat162_rn(make_float2(lo, hi));
            }
        }
        __syncthreads();
    }

    // ======================= decoder weight reload =========================
    float* sWdT = uni + U_WDT;                    // [256][129]
    for (int i = t; i < 128 * 256; i += NT_) {
        int ho = i >> 8, k = i & 255;
        sWdT[k * 129 + ho] = Wd[i];
    }
    if (t < 512) sBias[t] = bih_d[t] + bhh_d[t];
    for (int i = t; i < 768; i += NT_) sWo[i] = Wout[i];
    if (t < 3) sBo[t] = bout[t];
    __syncthreads();

    // ======================= decoder loop ==================================
    for (int st = 0; st < kHZ; st++) {
        // --- s1: a[r][ho] = W_d[ho] . [d;c]   (8 rows = 4 pairs)
        {
            const int ho = t & 127;
            const int p0 = (t >> 7) * 4;
            ull a[4] = {0ull, 0ull, 0ull, 0ull};
            #pragma unroll 4
            for (int k = 0; k < 128; k++) {
                float w = sWdT[k * 129 + ho];
                ull w2 = pk2(w, w);
                #pragma unroll
                for (int p = 0; p < 4; p++)
                    a[p] = ffma2(w2, ldp(sHpf + (k * 17 + p0 + p) * 2), a[p]);
            }
            #pragma unroll 4
            for (int k = 0; k < 128; k++) {
                float w = sWdT[(128 + k) * 129 + ho];
                ull w2 = pk2(w, w);
                #pragma unroll
                for (int p = 0; p < 4; p++)
                    a[p] = ffma2(w2, ldp(sCpf + (k * 17 + p0 + p) * 2), a[p]);
            }
            #pragma unroll
            for (int p = 0; p < 4; p++) stp(sApf + (ho * 17 + p0 + p) * 2, a[p]);
        }
        __syncthreads();
        // --- s2: logits[r][s] = sum_ho v_d[ho]*tanh(a[r][ho] + AEt[ho][s])
        {
            const int s  = t & 63;
            const int g  = t >> 6;                 // 0..7
            const int r0 = g * 4;                  // rows r0..r0+3 = pairs 2g,2g+1
            float l0 = 0.f, l1 = 0.f, l2 = 0.f, l3 = 0.f;
            const __nv_bfloat162* aet0 =
                g_AEtbf + ((size_t)(bp0 + 2 * g) * kH) * kS + s;
            const __nv_bfloat162* aet1 = aet0 + (size_t)kH * kS;
            #pragma unroll 4
            for (int ho = 0; ho < 128; ho++) {
                float2 v0 = __bfloat1622float2(aet0[ho * kS]);
                float2 v1 = __bfloat1622float2(aet1[ho * kS]);
                float w  = sVd[ho];
                float a0 = sApf[ho * 34 + r0];
                float a1 = sApf[ho * 34 + r0 + 1];
                float a2 = sApf[ho * 34 + r0 + 2];
                float a3 = sApf[ho * 34 + r0 + 3];
                l0 += w * tanhfast(a0 + v0.x);
                l1 += w * tanhfast(a1 + v0.y);
                l2 += w * tanhfast(a2 + v1.x);
                l3 += w * tanhfast(a3 + v1.y);
            }
            sLgf[s * 34 + r0]     = l0;
            sLgf[s * 34 + r0 + 1] = l1;
            sLgf[s * 34 + r0 + 2] = l2;
            sLgf[s * 34 + r0 + 3] = l3;
        }
        __syncthreads();
        // --- s3: softmax beta over s; phys vector (pair layouts)
        if (t < MB_) {
            const int r = t;
            float mx = -1e30f;
            for (int s2 = 0; s2 < 64; s2++) mx = fmaxf(mx, sLgf[s2 * 34 + r]);
            float sum = 0.f;
            for (int s2 = 0; s2 < 64; s2++) {
                float e = __expf(sLgf[s2 * 34 + r] - mx);
                sLgf[s2 * 34 + r] = e;
                sum += e;
            }
            float inv = __fdividef(1.f, sum);
            for (int s2 = 0; s2 < 64; s2++) sLgf[s2 * 34 + r] *= inv;
            #pragma unroll
            for (int m = 0; m < 3; m++) {
                sPhy[m * 34 + r]       = sPos[r * 4 + m] - sSc[6 + m];
                sPhy[(3 + m) * 34 + r] = __fdividef(sVel[r * 4 + m] - sSc[m], sSc[3 + m]);
                sPhy[(6 + m) * 34 + r] = __fdividef(sAcc[r * 4 + m], sSc[3 + m]);
            }
        }
        __syncthreads();
        // --- s4: context[r][ho] = sum_s beta[r][s]*EncH  (bf16 pairs)
        {
            const int ho = t & 127;
            const int p0 = (t >> 7) * 4;
            ull a[4] = {0ull, 0ull, 0ull, 0ull};
            const __nv_bfloat162* eh =
                g_EncHbf + ((size_t)(bp0 + p0) * kS) * kH + ho;
            #pragma unroll 4
            for (int s2 = 0; s2 < 64; s2++) {
                #pragma unroll
                for (int p = 0; p < 4; p++) {
                    float2 h2 = __bfloat1622float2(eh[(p * kS + s2) * kH]);
                    ull bv = ldp(sLgf + s2 * 34 + 2 * (p0 + p));
                    a[p] = ffma2(bv, pk2(h2.x, h2.y), a[p]);
                }
            }
            #pragma unroll
            for (int p = 0; p < 4; p++) stp(sApf + (ho * 17 + p0 + p) * 2, a[p]);
        }
        __syncthreads();
        // --- s5: decoder gates + LSTM update
        {
            const int j  = t & 127;
            const int p0 = (t >> 7) * 4;
            ull acc[16];
            {
                ull bi = pk2(sBias[j], sBias[j]);
                ull bf = pk2(sBias[128 + j], sBias[128 + j]);
                ull bg = pk2(sBias[256 + j], sBias[256 + j]);
                ull bo = pk2(sBias[384 + j], sBias[384 + j]);
                #pragma unroll
                for (int p = 0; p < 4; p++) {
                    acc[p] = bi; acc[4 + p] = bf; acc[8 + p] = bg; acc[12 + p] = bo;
                }
            }
            #pragma unroll
            for (int d = 0; d < 9; d++) {
                float4 w4 = g_Wdec4[d * 128 + j];
                ull wi = pk2(w4.x, w4.x), wf = pk2(w4.y, w4.y);
                ull wg = pk2(w4.z, w4.z), wo = pk2(w4.w, w4.w);
                #pragma unroll
                for (int p = 0; p < 4; p++) {
                    ull xv = ldp(sPhy + d * 34 + 2 * (p0 + p));
                    acc[p]      = ffma2(wi, xv, acc[p]);
                    acc[4 + p]  = ffma2(wf, xv, acc[4 + p]);
                    acc[8 + p]  = ffma2(wg, xv, acc[8 + p]);
                    acc[12 + p] = ffma2(wo, xv, acc[12 + p]);
                }
            }
            #pragma unroll 4
            for (int k = 0; k < 128; k++) {         // context part
                float4 w4 = g_Wdec4[(9 + k) * 128 + j];
                ull wi = pk2(w4.x, w4.x), wf = pk2(w4.y, w4.y);
                ull wg = pk2(w4.z, w4.z), wo = pk2(w4.w, w4.w);
                #pragma unroll
                for (int p = 0; p < 4; p++) {
                    ull xv = ldp(sApf + (k * 17 + p0 + p) * 2);
                    acc[p]      = ffma2(wi, xv, acc[p]);
                    acc[4 + p]  = ffma2(wf, xv, acc[4 + p]);
                    acc[8 + p]  = ffma2(wg, xv, acc[8 + p]);
                    acc[12 + p] = ffma2(wo, xv, acc[12 + p]);
                }
            }
            #pragma unroll 4
            for (int k = 0; k < 128; k++) {         // h part
                float4 w4 = g_Wdec4[(137 + k) * 128 + j];
                ull wi = pk2(w4.x, w4.x), wf = pk2(w4.y, w4.y);
                ull wg = pk2(w4.z, w4.z), wo = pk2(w4.w, w4.w);
                #pragma unroll
                for (int p = 0; p < 4; p++) {
                    ull hv = ldp(sHpf + (k * 17 + p0 + p) * 2);
                    acc[p]      = ffma2(wi, hv, acc[p]);
                    acc[4 + p]  = ffma2(wf, hv, acc[4 + p]);
                    acc[8 + p]  = ffma2(wg, hv, acc[8 + p]);
                    acc[12 + p] = ffma2(wo, hv, acc[12 + p]);
                }
            }
            __syncthreads();
            #pragma unroll
            for (int p = 0; p < 4; p++) {
                float ai0, ai1, af0, af1, ag0, ag1, ao0, ao1, c0, c1;
                upk2(acc[p], ai0, ai1);  upk2(acc[4 + p], af0, af1);
                upk2(acc[8 + p], ag0, ag1); upk2(acc[12 + p], ao0, ao1);
                upk2(ldp(sCpf + (j * 17 + p0 + p) * 2), c0, c1);
                float cn0 = sigm(af0) * c0 + sigm(ai0) * tanhacc(ag0);
                float cn1 = sigm(af1) * c1 + sigm(ai1) * tanhacc(ag1);
                float dn0 = sigm(ao0) * tanhacc(cn0);
                float dn1 = sigm(ao1) * tanhacc(cn1);
                stp(sCpf + (j * 17 + p0 + p) * 2, pk2(cn0, cn1));
                stp(sHpf + (j * 17 + p0 + p) * 2, pk2(dn0, dn1));
            }
        }
        __syncthreads();
        // --- s6: pred_acc + Verlet + output
        if (t < 96) {
            const int m = t >> 5;
            const int r = t & 31;
            float acc = sBo[m];
            #pragma unroll 4
            for (int k = 0; k < 128; k++) acc += sWo[m * 256 + k] * sHpf[k * 34 + r];
            #pragma unroll 4
            for (int k = 0; k < 128; k++) acc += sWo[m * 256 + 128 + k] * sApf[k * 34 + r];
            float pa   = acc * sSc[3 + m];
            float pos  = sPos[r * 4 + m];
            float vel  = sVel[r * 4 + m];
            float ac   = sAcc[r * 4 + m];
            float posn = pos + vel * kDT + 0.5f * ac * kDT * kDT;
            float veln = vel + 0.5f * (ac + pa) * kDT;
            float* orow = out + ((b0 + r) * kHZ + st) * 9;
            orow[m]     = posn;
            orow[3 + m] = veln;
            orow[6 + m] = pa;
            sPos[r * 4 + m] = posn;
            sVel[r * 4 + m] = veln;
            sAcc[r * 4 + m] = pa;
        }
        __syncthreads();
    }
}

// ---------------------------------------------------------------------------
extern "C" void kernel_launch(void* const* d_in, const int* in_sizes, int n_in,
                              void* d_out, int out_size) {
    const float* x      = (const float*)d_in[0];
    const float* Wih_e  = (const float*)d_in[1];
    const float* Whh_e  = (const float*)d_in[2];
    const float* bih_e  = (const float*)d_in[3];
    const float* bhh_e  = (const float*)d_in[4];
    const float* We     = (const float*)d_in[5];
    const float* Ve     = (const float*)d_in[6];
    const float* ve     = (const float*)d_in[7];
    const float* Wd     = (const float*)d_in[8];
    const float* Vd     = (const float*)d_in[9];
    const float* vd     = (const float*)d_in[10];
    const float* Wih_d  = (const float*)d_in[11];
    const float* Whh_d  = (const float*)d_in[12];
    const float* bih_d  = (const float*)d_in[13];
    const float* bhh_d  = (const float*)d_in[14];
    const float* Wout   = (const float*)d_in[15];
    const float* bout   = (const float*)d_in[16];
    const float* smean  = (const float*)d_in[17];
    const float* sstd   = (const float*)d_in[18];
    const float* pmean  = (const float*)d_in[19];
    float* out = (float*)d_out;

    cudaFuncSetAttribute(davinci_kernel,
                         cudaFuncAttributeMaxDynamicSharedMemorySize, SMEM_BYTES);

    prep_kernel<<<(265 * 128 + 255) / 256, 256>>>(Whh_e, Wih_e, Whh_d, Wih_d, Vd);
    davinci_kernel<<<kB / MB_, NT_, SMEM_BYTES>>>(
        x, bih_e, bhh_e, We, Ve, ve, Wd, vd,
        bih_d, bhh_d, Wout, bout, smean, sstd, pmean, out);
}